// round 16
// baseline (speedup 1.0000x reference)
#include <cuda_runtime.h>
#include <cuda_bf16.h>
#include <cstdint>

#define KBINS 8
#define BVAL 3.0f
#define DIMN 32
#define LNUM 31
#define NP 23
#define MIN_BW 1e-3f
#define MIN_D 1e-3f
#define BATCH 65536
#define NGRP 8
#define LPG 4            // layers per group (last group: 31 - 7*4 = 3)

// per-layer fragment buffer layout (uint32 units)
#define OFF_B1H 0
#define OFF_B1L 512
#define OFF_B2H 1024
#define OFF_B2L 1536
#define OFF_B3H 2048
#define OFF_B3L 2432
#define OFF_BI1 2816
#define OFF_BI2 3072
#define LSTRIDE 3328

__device__ __align__(16) uint32_t g_frag[LNUM * LSTRIDE];
__device__ float g_ldpart[NGRP * BATCH];    // per-layer-group log-det partials

// ---------------- packing helpers ----------------
__device__ __forceinline__ uint32_t pk_bf2(float v0, float v1) {
    uint32_t r;
    asm("cvt.rn.bf16x2.f32 %0, %1, %2;" : "=r"(r) : "f"(v1), "f"(v0));
    return r;
}
__device__ __forceinline__ float bf_lo(uint32_t p) { return __uint_as_float(p << 16); }
__device__ __forceinline__ float bf_hi(uint32_t p) { return __uint_as_float(p & 0xffff0000u); }

__device__ __forceinline__ void mma16816(float c[4], uint32_t a0, uint32_t a1,
                                         uint32_t a2, uint32_t a3,
                                         uint32_t b0, uint32_t b1) {
    asm volatile(
        "mma.sync.aligned.m16n8k16.row.col.f32.bf16.bf16.f32 "
        "{%0,%1,%2,%3}, {%4,%5,%6,%7}, {%8,%9}, {%0,%1,%2,%3};"
        : "+f"(c[0]), "+f"(c[1]), "+f"(c[2]), "+f"(c[3])
        : "r"(a0), "r"(a1), "r"(a2), "r"(a3), "r"(b0), "r"(b1));
}

// tanh with 1 MUFU (EX2) + Newton reciprocal on the FMA pipe.
// MUFU was the hidden binding resource (~75us busy); RCP moved to fma slack.
// d = e^{2x}+1 in [2, ~1e38]; bit-trick initial (~6% err) + 2 Newton -> 1.3e-5.
// Overflow-safe: pre-activations |x| <~ 6 << 44 (e^{2x} overflow point).
__device__ __forceinline__ float fast_tanh(float x) {
    float e = __expf(2.0f * x);              // FMUL-imm + MUFU.EX2
    float d = e + 1.0f;
    float y = __uint_as_float(0x7EF127EAu - __float_as_uint(d));
    y = y * (2.0f - d * y);                  // Newton 1 (FFMA + FMUL)
    y = y * (2.0f - d * y);                  // Newton 2
    return 1.0f - 2.0f * y;                  // FFMA
}

// ---------------- spline ----------------
__device__ __forceinline__ void softmax8_nm(const float* p, float scale, float* out) {
    float s = 0.0f;
#pragma unroll
    for (int i = 0; i < KBINS; i++) { out[i] = __expf(p[i]); s += out[i]; }
    float inv = __fdividef(scale, s);
#pragma unroll
    for (int i = 0; i < KBINS; i++) out[i] *= inv;
}

__device__ __forceinline__ float spline_fwd(float xin, const float* p, float* ldo) {
    float cw[KBINS + 1], ch[KBINS + 1];
    {
        float wu[KBINS], w_[KBINS];
        softmax8_nm(p, 2.0f * BVAL, wu);
        softmax8_nm(wu, 1.0f - MIN_BW * KBINS, w_);
        cw[0] = -BVAL;
        float c = 0.0f;
#pragma unroll
        for (int k = 0; k < KBINS; k++) { c += w_[k] + MIN_BW; cw[k + 1] = 2.0f * BVAL * c - BVAL; }
        cw[KBINS] = BVAL;
    }
    {
        float hu[KBINS], h_[KBINS];
        softmax8_nm(p + KBINS, 2.0f * BVAL, hu);
        softmax8_nm(hu, 1.0f - MIN_BW * KBINS, h_);
        ch[0] = -BVAL;
        float c = 0.0f;
#pragma unroll
        for (int k = 0; k < KBINS; k++) { c += h_[k] + MIN_BW; ch[k + 1] = 2.0f * BVAL * c - BVAL; }
        ch[KBINS] = BVAL;
    }
    // derivs: softplus(softplus(t)) == log(2 + e^t) exactly; edges pinned to 1
    float dv[KBINS + 1];
    dv[0] = 1.0f; dv[KBINS] = 1.0f;
#pragma unroll
    for (int j = 0; j < KBINS - 1; j++)
        dv[j + 1] = MIN_D + __logf(2.0f + __expf(p[2 * KBINS + j]));

    bool inside = (xin >= -BVAL) && (xin <= BVAL);
    float xc = fminf(fmaxf(xin, -BVAL), BVAL);
    float in_cw = cw[0], in_ch = ch[0];
    float in_w = cw[1] - cw[0], in_h = ch[1] - ch[0];
    float d0 = dv[0], d1 = dv[1];
#pragma unroll
    for (int k = 1; k < KBINS; k++) {
        if (xc >= cw[k]) {
            in_cw = cw[k]; in_ch = ch[k];
            in_w = cw[k + 1] - cw[k]; in_h = ch[k + 1] - ch[k];
            d0 = dv[k]; d1 = dv[k + 1];
        }
    }
    float invw = __fdividef(1.0f, in_w);
    float delta = in_h * invw;
    float th = (xc - in_cw) * invw;
    float tt = th * (1.0f - th);
    float num = in_h * (delta * th * th + d0 * tt);
    float den = delta + (d0 + d1 - 2.0f * delta) * tt;
    float invden = __frcp_rn(den);
    float outv = in_ch + num * invden;
    float omt = 1.0f - th;
    float dnum = delta * delta * (d1 * th * th + 2.0f * delta * tt + d0 * omt * omt);
    float ld = __logf(dnum * invden * invden);
    *ldo = inside ? ld : 0.0f;
    return inside ? outv : xin;
}

// ---------------- prep kernel: build fragment buffer once ----------------
__device__ __forceinline__ void stage_bfr_g(const float* __restrict__ W, int NT,
                                            int kmax, int ncols,
                                            uint32_t* hi, uint32_t* lo, int t) {
    int total = 2 * NT * 32;
    for (int i = t; i < total; i += 128) {
        int lane = i & 31;
        int tile = i >> 5;
        int nt = tile % NT, kt = tile / NT;
        int n  = nt * 8 + (lane >> 2);
        int kb = kt * 16 + 2 * (lane & 3);
#pragma unroll
        for (int r = 0; r < 2; r++) {
            int k0 = kb + r * 8;
            float v0 = (k0     < kmax && n < ncols) ? W[k0 * ncols + n]       : 0.0f;
            float v1 = (k0 + 1 < kmax && n < ncols) ? W[(k0 + 1) * ncols + n] : 0.0f;
            uint32_t h = pk_bf2(v0, v1);
            uint32_t l = pk_bf2(v0 - bf_lo(h), v1 - bf_hi(h));
            hi[i * 2 + r] = h;
            lo[i * 2 + r] = l;
        }
    }
}

// grid (LNUM, 4): y selects the section -> 124 small blocks (latency parallelism)
__global__ __launch_bounds__(128) void nsf_prep_kernel(
    const float* __restrict__ w1, const float* __restrict__ b1,
    const float* __restrict__ w2, const float* __restrict__ b2,
    const float* __restrict__ w3)
{
    const int l = blockIdx.x;
    const int sec = blockIdx.y;
    const int t = threadIdx.x;
    uint32_t* gb = g_frag + l * LSTRIDE;
    if (sec == 0) {
        stage_bfr_g(w1 + l * 992,  4, 31, 32, gb + OFF_B1H, gb + OFF_B1L, t);
    } else if (sec == 1) {
        stage_bfr_g(w2 + l * 1024, 4, 32, 32, gb + OFF_B2H, gb + OFF_B2L, t);
    } else if (sec == 2) {
        stage_bfr_g(w3 + l * 736,  3, 32, NP, gb + OFF_B3H, gb + OFF_B3L, t);
    } else {
        int nt = t >> 5, lane = t & 31;
        int col = nt * 8 + 2 * (lane & 3);
        float2 v1 = make_float2(b1[l * 32 + col], b1[l * 32 + col + 1]);
        float2 v2 = make_float2(b2[l * 32 + col], b2[l * 32 + col + 1]);
        *(float2*)(gb + OFF_BI1 + t * 2) = v1;
        *(float2*)(gb + OFF_BI2 + t * 2) = v2;
    }
}

// ---------------- ld reduce kernel ----------------
__global__ __launch_bounds__(256) void nsf_ld_reduce(float* __restrict__ ldout) {
    int b = blockIdx.x * 256 + threadIdx.x;
    float s = 0.0f;
#pragma unroll
    for (int g = 0; g < NGRP; g++) s += g_ldpart[g * BATCH + b];
    ldout[b] = s;
}

// ---------------- main kernel pieces ----------------
template <int NT>
__device__ __forceinline__ void initC(float c[2][4][4], const uint32_t* bi, int lane) {
#pragma unroll
    for (int nt = 0; nt < NT; nt++) {
        float2 bv = __ldg((const float2*)(bi + (nt * 32 + lane) * 2));
#pragma unroll
        for (int m = 0; m < 2; m++) {
            c[m][nt][0] = bv.x; c[m][nt][1] = bv.y;
            c[m][nt][2] = bv.x; c[m][nt][3] = bv.y;
        }
    }
}

// 3-term GEMM, A in registers: bh loaded once (AhBh + AlBh), then bl (AhBl)
template <int NT>
__device__ __forceinline__ void gemm_regA(float c[2][4][4],
                                          const uint32_t ah[2][2][4],
                                          const uint32_t al[2][2][4],
                                          const uint32_t* __restrict__ gbh,
                                          const uint32_t* __restrict__ gbl,
                                          int lane) {
#pragma unroll
    for (int kt = 0; kt < 2; kt++) {
        uint32_t bf[NT][2];
#pragma unroll
        for (int nt = 0; nt < NT; nt++) {
            uint2 v = __ldg((const uint2*)(gbh + ((kt * NT + nt) * 32 + lane) * 2));
            bf[nt][0] = v.x; bf[nt][1] = v.y;
        }
#pragma unroll
        for (int m = 0; m < 2; m++)
#pragma unroll
            for (int nt = 0; nt < NT; nt++)
                mma16816(c[m][nt], ah[kt][m][0], ah[kt][m][1], ah[kt][m][2], ah[kt][m][3],
                         bf[nt][0], bf[nt][1]);
#pragma unroll
        for (int m = 0; m < 2; m++)
#pragma unroll
            for (int nt = 0; nt < NT; nt++)
                mma16816(c[m][nt], al[kt][m][0], al[kt][m][1], al[kt][m][2], al[kt][m][3],
                         bf[nt][0], bf[nt][1]);
#pragma unroll
        for (int nt = 0; nt < NT; nt++) {
            uint2 v = __ldg((const uint2*)(gbl + ((kt * NT + nt) * 32 + lane) * 2));
            bf[nt][0] = v.x; bf[nt][1] = v.y;
        }
#pragma unroll
        for (int m = 0; m < 2; m++)
#pragma unroll
            for (int nt = 0; nt < NT; nt++)
                mma16816(c[m][nt], ah[kt][m][0], ah[kt][m][1], ah[kt][m][2], ah[kt][m][3],
                         bf[nt][0], bf[nt][1]);
    }
}

// 3-term GEMM, A (x fragments) from per-thread smem slots
template <int NT>
__device__ __forceinline__ void gemm_smemA(float c[2][4][4], const uint4* axs,
                                           const uint32_t* __restrict__ gbh,
                                           const uint32_t* __restrict__ gbl,
                                           int lane, int t) {
#pragma unroll
    for (int kt = 0; kt < 2; kt++) {
        uint4 Ah[2], Al[2];
#pragma unroll
        for (int m = 0; m < 2; m++) {
            Ah[m] = axs[(0 * 4 + kt * 2 + m) * 128 + t];
            Al[m] = axs[(1 * 4 + kt * 2 + m) * 128 + t];
        }
        uint32_t bf[NT][2];
#pragma unroll
        for (int nt = 0; nt < NT; nt++) {
            uint2 v = __ldg((const uint2*)(gbh + ((kt * NT + nt) * 32 + lane) * 2));
            bf[nt][0] = v.x; bf[nt][1] = v.y;
        }
#pragma unroll
        for (int m = 0; m < 2; m++)
#pragma unroll
            for (int nt = 0; nt < NT; nt++)
                mma16816(c[m][nt], Ah[m].x, Ah[m].y, Ah[m].z, Ah[m].w, bf[nt][0], bf[nt][1]);
#pragma unroll
        for (int m = 0; m < 2; m++)
#pragma unroll
            for (int nt = 0; nt < NT; nt++)
                mma16816(c[m][nt], Al[m].x, Al[m].y, Al[m].z, Al[m].w, bf[nt][0], bf[nt][1]);
#pragma unroll
        for (int nt = 0; nt < NT; nt++) {
            uint2 v = __ldg((const uint2*)(gbl + ((kt * NT + nt) * 32 + lane) * 2));
            bf[nt][0] = v.x; bf[nt][1] = v.y;
        }
#pragma unroll
        for (int m = 0; m < 2; m++)
#pragma unroll
            for (int nt = 0; nt < NT; nt++)
                mma16816(c[m][nt], Ah[m].x, Ah[m].y, Ah[m].z, Ah[m].w, bf[nt][0], bf[nt][1]);
    }
}

__device__ __forceinline__ void epi_tanh(const float c[2][4][4],
                                         uint32_t ah[2][2][4], uint32_t al[2][2][4]) {
#pragma unroll
    for (int m = 0; m < 2; m++)
#pragma unroll
        for (int kt = 0; kt < 2; kt++)
#pragma unroll
            for (int half = 0; half < 2; half++) {
                int nt = 2 * kt + half;
                float t0 = fast_tanh(c[m][nt][0]);
                float t1 = fast_tanh(c[m][nt][1]);
                float t2 = fast_tanh(c[m][nt][2]);
                float t3 = fast_tanh(c[m][nt][3]);
                uint32_t h01 = pk_bf2(t0, t1);
                uint32_t h23 = pk_bf2(t2, t3);
                ah[kt][m][2 * half]     = h01;
                ah[kt][m][2 * half + 1] = h23;
                al[kt][m][2 * half]     = pk_bf2(t0 - bf_lo(h01), t1 - bf_hi(h01));
                al[kt][m][2 * half + 1] = pk_bf2(t2 - bf_lo(h23), t3 - bf_hi(h23));
            }
}

// grid (512, NGRP): blockIdx.x = batch tile, blockIdx.y = layer group (LPG layers).
// Layers are mutually independent (causality baked into pre-masked w1).
__global__ __launch_bounds__(128, 5) void nsf_mma_kernel(
    const float* __restrict__ x, const float* __restrict__ init_param,
    const float* __restrict__ b3,
    float* __restrict__ zout)
{
    __shared__ uint4 axs[8 * 128];      // per-thread-private x A-fragments, 16KB
    __shared__ float pbuf[128 * 25];    // warp-private GEMM3 param bounce, stride 25

    const int t = threadIdx.x;
    const int lane = t & 31;
    const int wp = t >> 5;
    const int b0 = blockIdx.x * 128;
    const int b = b0 + t;
    const int grp = blockIdx.y;
    const int l0 = grp * LPG;
    const int lcnt = (grp == NGRP - 1) ? (LNUM - LPG * (NGRP - 1)) : LPG;

    // build x A-fragments directly from gmem (own-thread smem slots; no barrier)
#pragma unroll
    for (int kt = 0; kt < 2; kt++)
#pragma unroll
        for (int m = 0; m < 2; m++) {
            int r0 = b0 + wp * 32 + m * 16 + (lane >> 2);
            int k0 = kt * 16 + 2 * (lane & 3);
            const float* xr  = x + (size_t)r0 * 32;
            const float* xr8 = xr + 8 * 32;
            float v00 = xr[k0],      v01 = xr[k0 + 1];
            float v10 = xr8[k0],     v11 = xr8[k0 + 1];
            float v20 = xr[k0 + 8],  v21 = xr[k0 + 9];
            float v30 = xr8[k0 + 8], v31 = xr8[k0 + 9];
            uint4 h, l;
            h.x = pk_bf2(v00, v01); l.x = pk_bf2(v00 - bf_lo(h.x), v01 - bf_hi(h.x));
            h.y = pk_bf2(v10, v11); l.y = pk_bf2(v10 - bf_lo(h.y), v11 - bf_hi(h.y));
            h.z = pk_bf2(v20, v21); l.z = pk_bf2(v20 - bf_lo(h.z), v21 - bf_hi(h.z));
            h.w = pk_bf2(v30, v31); l.w = pk_bf2(v30 - bf_lo(h.w), v31 - bf_hi(h.w));
            axs[(0 * 4 + kt * 2 + m) * 128 + t] = h;
            axs[(1 * 4 + kt * 2 + m) * 128 + t] = l;
        }

    float ldacc = 0.0f;
    // dim-0 spline handled by group 0 only (uniform init_param)
    if (grp == 0) {
        float p[NP];
#pragma unroll
        for (int j = 0; j < NP; j++) p[j] = init_param[j];
        float ld;
        zout[(size_t)b * DIMN] = spline_fwd(__ldg(&x[(size_t)b * 32]), p, &ld);
        ldacc = ld;
    }

    const uint32_t* gb = g_frag + l0 * LSTRIDE;
    for (int li = 0; li < lcnt; li++, gb += LSTRIDE) {
        const int l = l0 + li;
        float c[2][4][4];
        uint32_t ah[2][2][4], al[2][2][4];

        // GEMM1: h1 = tanh(x @ w1 + b1)
        initC<4>(c, gb + OFF_BI1, lane);
        gemm_smemA<4>(c, axs, gb + OFF_B1H, gb + OFF_B1L, lane, t);
        epi_tanh(c, ah, al);

        // GEMM2: h2 = tanh(h1 @ w2 + b2)
        initC<4>(c, gb + OFF_BI2, lane);
        gemm_regA<4>(c, ah, al, gb + OFF_B2H, gb + OFF_B2L, lane);
        epi_tanh(c, ah, al);

        // GEMM3: p = h2 @ w3 (bias at gather)
#pragma unroll
        for (int m = 0; m < 2; m++)
#pragma unroll
            for (int nt = 0; nt < 3; nt++)
#pragma unroll
                for (int r = 0; r < 4; r++) c[m][nt][r] = 0.0f;
        gemm_regA<3>(c, ah, al, gb + OFF_B3H, gb + OFF_B3L, lane);

        // scatter params (warp-private rows; stride 25 conflict-free)
#pragma unroll
        for (int m = 0; m < 2; m++) {
            int r0 = wp * 32 + m * 16 + (lane >> 2);
            int q2 = 2 * (lane & 3);
#pragma unroll
            for (int nt = 0; nt < 3; nt++) {
                int col = nt * 8 + q2;
                pbuf[r0 * 25 + col]           = c[m][nt][0];
                pbuf[r0 * 25 + col + 1]       = c[m][nt][1];
                pbuf[(r0 + 8) * 25 + col]     = c[m][nt][2];
                pbuf[(r0 + 8) * 25 + col + 1] = c[m][nt][3];
            }
        }
        __syncwarp();

        // gather own row (+ b3 broadcast), spline for dim l+1
        {
            const float* b3l = b3 + l * NP;
            float p[NP];
#pragma unroll
            for (int j = 0; j < NP; j++) p[j] = pbuf[t * 25 + j] + __ldg(&b3l[j]);
            float ld;
            float xv = __ldg(&x[(size_t)b * 32 + l + 1]);   // L1-resident after prologue
            zout[(size_t)b * DIMN + l + 1] = spline_fwd(xv, p, &ld);
            ldacc += ld;
        }
        __syncwarp();   // protect pbuf before next layer's scatter
    }

    g_ldpart[grp * BATCH + b] = ldacc;
}

extern "C" void kernel_launch(void* const* d_in, const int* in_sizes, int n_in,
                              void* d_out, int out_size) {
    const float* x          = (const float*)d_in[0];
    const float* init_param = (const float*)d_in[1];
    const float* w1 = (const float*)d_in[2];
    const float* b1 = (const float*)d_in[3];
    const float* w2 = (const float*)d_in[4];
    const float* b2 = (const float*)d_in[5];
    const float* w3 = (const float*)d_in[6];
    const float* b3 = (const float*)d_in[7];

    float* out = (float*)d_out;
    int write_ld = (out_size >= BATCH * DIMN + BATCH) ? 1 : 0;

    dim3 pgrid(LNUM, 4);
    nsf_prep_kernel<<<pgrid, 128>>>(w1, b1, w2, b2, w3);
    dim3 grid(BATCH / 128, NGRP);
    nsf_mma_kernel<<<grid, 128>>>(x, init_param, b3, out);
    if (write_ld)
        nsf_ld_reduce<<<BATCH / 256, 256>>>(out + (size_t)BATCH * DIMN);
}

// round 17
// speedup vs baseline: 1.1460x; 1.1460x over previous
#include <cuda_runtime.h>
#include <cuda_bf16.h>
#include <cstdint>

#define KBINS 8
#define BVAL 3.0f
#define DIMN 32
#define LNUM 31
#define NP 23
#define MIN_BW 1e-3f
#define MIN_D 1e-3f
#define BATCH 65536
#define NGRP 8
#define LPG 4            // layers per group (last group: 31 - 7*4 = 3)
#define PSTRIDE 28       // pbuf row stride (floats): conflict-free + 16B-aligned rows

// per-layer fragment buffer layout (uint32 units); B sections store uint4
// {bh0, bh1, bl0, bl1} per (tile, lane)
#define OFF_B1  0        // 2*4*32 uint4 = 1024 u32
#define OFF_B2  1024
#define OFF_B3  2048     // 2*3*32 uint4 = 768 u32
#define OFF_BI1 2816
#define OFF_BI2 3072
#define LSTRIDE 3328

__device__ __align__(16) uint32_t g_frag[LNUM * LSTRIDE];
__device__ float g_ldpart[NGRP * BATCH];    // per-layer-group log-det partials

// ---------------- packing helpers ----------------
__device__ __forceinline__ uint32_t pk_bf2(float v0, float v1) {
    uint32_t r;
    asm("cvt.rn.bf16x2.f32 %0, %1, %2;" : "=r"(r) : "f"(v1), "f"(v0));
    return r;
}
__device__ __forceinline__ float bf_lo(uint32_t p) { return __uint_as_float(p << 16); }
__device__ __forceinline__ float bf_hi(uint32_t p) { return __uint_as_float(p & 0xffff0000u); }

__device__ __forceinline__ void mma16816(float c[4], uint32_t a0, uint32_t a1,
                                         uint32_t a2, uint32_t a3,
                                         uint32_t b0, uint32_t b1) {
    asm volatile(
        "mma.sync.aligned.m16n8k16.row.col.f32.bf16.bf16.f32 "
        "{%0,%1,%2,%3}, {%4,%5,%6,%7}, {%8,%9}, {%0,%1,%2,%3};"
        : "+f"(c[0]), "+f"(c[1]), "+f"(c[2]), "+f"(c[3])
        : "r"(a0), "r"(a1), "r"(a2), "r"(a3), "r"(b0), "r"(b1));
}

// exp-based tanh — R15 proven form. (tanh.approx shares the tensor pipe [R10];
// Newton-rcp costs more issue slots than it saves MUFU [R16].)
__device__ __forceinline__ float fast_tanh(float x) {
    float e = __expf(2.0f * x);
    return 1.0f - __fdividef(2.0f, e + 1.0f);
}

// ---------------- spline ----------------
__device__ __forceinline__ void softmax8_nm(const float* p, float scale, float* out) {
    float s = 0.0f;
#pragma unroll
    for (int i = 0; i < KBINS; i++) { out[i] = __expf(p[i]); s += out[i]; }
    float inv = __fdividef(scale, s);
#pragma unroll
    for (int i = 0; i < KBINS; i++) out[i] *= inv;
}

__device__ __forceinline__ float spline_fwd(float xin, const float* p, float* ldo) {
    float cw[KBINS + 1], ch[KBINS + 1];
    {
        float wu[KBINS], w_[KBINS];
        softmax8_nm(p, 2.0f * BVAL, wu);
        softmax8_nm(wu, 1.0f - MIN_BW * KBINS, w_);
        cw[0] = -BVAL;
        float c = 0.0f;
#pragma unroll
        for (int k = 0; k < KBINS; k++) { c += w_[k] + MIN_BW; cw[k + 1] = 2.0f * BVAL * c - BVAL; }
        cw[KBINS] = BVAL;
    }
    {
        float hu[KBINS], h_[KBINS];
        softmax8_nm(p + KBINS, 2.0f * BVAL, hu);
        softmax8_nm(hu, 1.0f - MIN_BW * KBINS, h_);
        ch[0] = -BVAL;
        float c = 0.0f;
#pragma unroll
        for (int k = 0; k < KBINS; k++) { c += h_[k] + MIN_BW; ch[k + 1] = 2.0f * BVAL * c - BVAL; }
        ch[KBINS] = BVAL;
    }
    // derivs: softplus(softplus(t)) == log(2 + e^t) exactly; edges pinned to 1
    float dv[KBINS + 1];
    dv[0] = 1.0f; dv[KBINS] = 1.0f;
#pragma unroll
    for (int j = 0; j < KBINS - 1; j++)
        dv[j + 1] = MIN_D + __logf(2.0f + __expf(p[2 * KBINS + j]));

    bool inside = (xin >= -BVAL) && (xin <= BVAL);
    float xc = fminf(fmaxf(xin, -BVAL), BVAL);
    float in_cw = cw[0], in_ch = ch[0];
    float in_w = cw[1] - cw[0], in_h = ch[1] - ch[0];
    float d0 = dv[0], d1 = dv[1];
#pragma unroll
    for (int k = 1; k < KBINS; k++) {
        if (xc >= cw[k]) {
            in_cw = cw[k]; in_ch = ch[k];
            in_w = cw[k + 1] - cw[k]; in_h = ch[k + 1] - ch[k];
            d0 = dv[k]; d1 = dv[k + 1];
        }
    }
    float invw = __fdividef(1.0f, in_w);
    float delta = in_h * invw;
    float th = (xc - in_cw) * invw;
    float tt = th * (1.0f - th);
    float num = in_h * (delta * th * th + d0 * tt);
    float den = delta + (d0 + d1 - 2.0f * delta) * tt;
    float invden = __frcp_rn(den);
    float outv = in_ch + num * invden;
    float omt = 1.0f - th;
    float dnum = delta * delta * (d1 * th * th + 2.0f * delta * tt + d0 * omt * omt);
    float ld = __logf(dnum * invden * invden);
    *ldo = inside ? ld : 0.0f;
    return inside ? outv : xin;
}

// ---------------- prep kernel: build fragment buffer once ----------------
// writes uint4 {bh0, bh1, bl0, bl1} per (tile, lane)
__device__ __forceinline__ void stage_bfr_g(const float* __restrict__ W, int NT,
                                            int kmax, int ncols,
                                            uint32_t* dst, int t) {
    int total = 2 * NT * 32;
    for (int i = t; i < total; i += 128) {
        int lane = i & 31;
        int tile = i >> 5;
        int nt = tile % NT, kt = tile / NT;
        int n  = nt * 8 + (lane >> 2);
        int kb = kt * 16 + 2 * (lane & 3);
        uint32_t h[2], l[2];
#pragma unroll
        for (int r = 0; r < 2; r++) {
            int k0 = kb + r * 8;
            float v0 = (k0     < kmax && n < ncols) ? W[k0 * ncols + n]       : 0.0f;
            float v1 = (k0 + 1 < kmax && n < ncols) ? W[(k0 + 1) * ncols + n] : 0.0f;
            h[r] = pk_bf2(v0, v1);
            l[r] = pk_bf2(v0 - bf_lo(h[r]), v1 - bf_hi(h[r]));
        }
        uint4 v; v.x = h[0]; v.y = h[1]; v.z = l[0]; v.w = l[1];
        *(uint4*)(dst + i * 4) = v;
    }
}

// grid (LNUM, 4): y selects the section -> 124 small blocks (latency parallelism)
__global__ __launch_bounds__(128) void nsf_prep_kernel(
    const float* __restrict__ w1, const float* __restrict__ b1,
    const float* __restrict__ w2, const float* __restrict__ b2,
    const float* __restrict__ w3)
{
    const int l = blockIdx.x;
    const int sec = blockIdx.y;
    const int t = threadIdx.x;
    uint32_t* gb = g_frag + l * LSTRIDE;
    if (sec == 0) {
        stage_bfr_g(w1 + l * 992,  4, 31, 32, gb + OFF_B1, t);
    } else if (sec == 1) {
        stage_bfr_g(w2 + l * 1024, 4, 32, 32, gb + OFF_B2, t);
    } else if (sec == 2) {
        stage_bfr_g(w3 + l * 736,  3, 32, NP, gb + OFF_B3, t);
    } else {
        int nt = t >> 5, lane = t & 31;
        int col = nt * 8 + 2 * (lane & 3);
        float2 v1 = make_float2(b1[l * 32 + col], b1[l * 32 + col + 1]);
        float2 v2 = make_float2(b2[l * 32 + col], b2[l * 32 + col + 1]);
        *(float2*)(gb + OFF_BI1 + t * 2) = v1;
        *(float2*)(gb + OFF_BI2 + t * 2) = v2;
    }
}

// ---------------- ld reduce kernel ----------------
__global__ __launch_bounds__(256) void nsf_ld_reduce(float* __restrict__ ldout) {
    int b = blockIdx.x * 256 + threadIdx.x;
    float s = 0.0f;
#pragma unroll
    for (int g = 0; g < NGRP; g++) s += g_ldpart[g * BATCH + b];
    ldout[b] = s;
}

// ---------------- main kernel pieces ----------------
template <int NT>
__device__ __forceinline__ void initC(float c[2][4][4], const uint32_t* bi, int lane) {
#pragma unroll
    for (int nt = 0; nt < NT; nt++) {
        float2 bv = __ldg((const float2*)(bi + (nt * 32 + lane) * 2));
#pragma unroll
        for (int m = 0; m < 2; m++) {
            c[m][nt][0] = bv.x; c[m][nt][1] = bv.y;
            c[m][nt][2] = bv.x; c[m][nt][3] = bv.y;
        }
    }
}

// 3-term GEMM, A in registers; B hi+lo arrive in one LDG.128 per (tile,lane)
template <int NT>
__device__ __forceinline__ void gemm_regA(float c[2][4][4],
                                          const uint32_t ah[2][2][4],
                                          const uint32_t al[2][2][4],
                                          const uint32_t* __restrict__ gbf,
                                          int lane) {
#pragma unroll
    for (int kt = 0; kt < 2; kt++) {
        uint4 bf[NT];
#pragma unroll
        for (int nt = 0; nt < NT; nt++)
            bf[nt] = __ldg((const uint4*)(gbf + ((kt * NT + nt) * 32 + lane) * 4));
#pragma unroll
        for (int m = 0; m < 2; m++)
#pragma unroll
            for (int nt = 0; nt < NT; nt++)
                mma16816(c[m][nt], ah[kt][m][0], ah[kt][m][1], ah[kt][m][2], ah[kt][m][3],
                         bf[nt].x, bf[nt].y);
#pragma unroll
        for (int m = 0; m < 2; m++)
#pragma unroll
            for (int nt = 0; nt < NT; nt++)
                mma16816(c[m][nt], al[kt][m][0], al[kt][m][1], al[kt][m][2], al[kt][m][3],
                         bf[nt].x, bf[nt].y);
#pragma unroll
        for (int m = 0; m < 2; m++)
#pragma unroll
            for (int nt = 0; nt < NT; nt++)
                mma16816(c[m][nt], ah[kt][m][0], ah[kt][m][1], ah[kt][m][2], ah[kt][m][3],
                         bf[nt].z, bf[nt].w);
    }
}

// 3-term GEMM, A (x fragments) from per-thread smem slots
template <int NT>
__device__ __forceinline__ void gemm_smemA(float c[2][4][4], const uint4* axs,
                                           const uint32_t* __restrict__ gbf,
                                           int lane, int t) {
#pragma unroll
    for (int kt = 0; kt < 2; kt++) {
        uint4 Ah[2], Al[2];
#pragma unroll
        for (int m = 0; m < 2; m++) {
            Ah[m] = axs[(0 * 4 + kt * 2 + m) * 128 + t];
            Al[m] = axs[(1 * 4 + kt * 2 + m) * 128 + t];
        }
        uint4 bf[NT];
#pragma unroll
        for (int nt = 0; nt < NT; nt++)
            bf[nt] = __ldg((const uint4*)(gbf + ((kt * NT + nt) * 32 + lane) * 4));
#pragma unroll
        for (int m = 0; m < 2; m++)
#pragma unroll
            for (int nt = 0; nt < NT; nt++)
                mma16816(c[m][nt], Ah[m].x, Ah[m].y, Ah[m].z, Ah[m].w, bf[nt].x, bf[nt].y);
#pragma unroll
        for (int m = 0; m < 2; m++)
#pragma unroll
            for (int nt = 0; nt < NT; nt++)
                mma16816(c[m][nt], Al[m].x, Al[m].y, Al[m].z, Al[m].w, bf[nt].x, bf[nt].y);
#pragma unroll
        for (int m = 0; m < 2; m++)
#pragma unroll
            for (int nt = 0; nt < NT; nt++)
                mma16816(c[m][nt], Ah[m].x, Ah[m].y, Ah[m].z, Ah[m].w, bf[nt].z, bf[nt].w);
    }
}

__device__ __forceinline__ void epi_tanh(const float c[2][4][4],
                                         uint32_t ah[2][2][4], uint32_t al[2][2][4]) {
#pragma unroll
    for (int m = 0; m < 2; m++)
#pragma unroll
        for (int kt = 0; kt < 2; kt++)
#pragma unroll
            for (int half = 0; half < 2; half++) {
                int nt = 2 * kt + half;
                float t0 = fast_tanh(c[m][nt][0]);
                float t1 = fast_tanh(c[m][nt][1]);
                float t2 = fast_tanh(c[m][nt][2]);
                float t3 = fast_tanh(c[m][nt][3]);
                uint32_t h01 = pk_bf2(t0, t1);
                uint32_t h23 = pk_bf2(t2, t3);
                ah[kt][m][2 * half]     = h01;
                ah[kt][m][2 * half + 1] = h23;
                al[kt][m][2 * half]     = pk_bf2(t0 - bf_lo(h01), t1 - bf_hi(h01));
                al[kt][m][2 * half + 1] = pk_bf2(t2 - bf_lo(h23), t3 - bf_hi(h23));
            }
}

// grid (512, NGRP): blockIdx.x = batch tile, blockIdx.y = layer group (LPG layers).
__global__ __launch_bounds__(128, 5) void nsf_mma_kernel(
    const float* __restrict__ x, const float* __restrict__ init_param,
    const float* __restrict__ b3,
    float* __restrict__ zout)
{
    __shared__ uint4 axs[8 * 128];                        // per-thread x A-fragments, 16KB
    __shared__ __align__(16) float pbuf[128 * PSTRIDE];   // param bounce, 14.3KB

    const int t = threadIdx.x;
    const int lane = t & 31;
    const int wp = t >> 5;
    const int b0 = blockIdx.x * 128;
    const int b = b0 + t;
    const int grp = blockIdx.y;
    const int l0 = grp * LPG;
    const int lcnt = (grp == NGRP - 1) ? (LNUM - LPG * (NGRP - 1)) : LPG;

    // build x A-fragments directly from gmem (own-thread smem slots; no barrier)
#pragma unroll
    for (int kt = 0; kt < 2; kt++)
#pragma unroll
        for (int m = 0; m < 2; m++) {
            int r0 = b0 + wp * 32 + m * 16 + (lane >> 2);
            int k0 = kt * 16 + 2 * (lane & 3);
            const float* xr  = x + (size_t)r0 * 32;
            const float* xr8 = xr + 8 * 32;
            float v00 = xr[k0],      v01 = xr[k0 + 1];
            float v10 = xr8[k0],     v11 = xr8[k0 + 1];
            float v20 = xr[k0 + 8],  v21 = xr[k0 + 9];
            float v30 = xr8[k0 + 8], v31 = xr8[k0 + 9];
            uint4 h, l;
            h.x = pk_bf2(v00, v01); l.x = pk_bf2(v00 - bf_lo(h.x), v01 - bf_hi(h.x));
            h.y = pk_bf2(v10, v11); l.y = pk_bf2(v10 - bf_lo(h.y), v11 - bf_hi(h.y));
            h.z = pk_bf2(v20, v21); l.z = pk_bf2(v20 - bf_lo(h.z), v21 - bf_hi(h.z));
            h.w = pk_bf2(v30, v31); l.w = pk_bf2(v30 - bf_lo(h.w), v31 - bf_hi(h.w));
            axs[(0 * 4 + kt * 2 + m) * 128 + t] = h;
            axs[(1 * 4 + kt * 2 + m) * 128 + t] = l;
        }

    float ldacc = 0.0f;
    // dim-0 spline handled by group 0 only (uniform init_param)
    if (grp == 0) {
        float p[NP];
#pragma unroll
        for (int j = 0; j < NP; j++) p[j] = init_param[j];
        float ld;
        zout[(size_t)b * DIMN] = spline_fwd(__ldg(&x[(size_t)b * 32]), p, &ld);
        ldacc = ld;
    }

    const uint32_t* gb = g_frag + l0 * LSTRIDE;
    for (int li = 0; li < lcnt; li++, gb += LSTRIDE) {
        const int l = l0 + li;
        float c[2][4][4];
        uint32_t ah[2][2][4], al[2][2][4];

        // GEMM1: h1 = tanh(x @ w1 + b1)
        initC<4>(c, gb + OFF_BI1, lane);
        gemm_smemA<4>(c, axs, gb + OFF_B1, lane, t);
        epi_tanh(c, ah, al);

        // GEMM2: h2 = tanh(h1 @ w2 + b2)
        initC<4>(c, gb + OFF_BI2, lane);
        gemm_regA<4>(c, ah, al, gb + OFF_B2, lane);
        epi_tanh(c, ah, al);

        // GEMM3: p = h2 @ w3 (bias at gather)
#pragma unroll
        for (int m = 0; m < 2; m++)
#pragma unroll
            for (int nt = 0; nt < 3; nt++)
#pragma unroll
                for (int r = 0; r < 4; r++) c[m][nt][r] = 0.0f;
        gemm_regA<3>(c, ah, al, gb + OFF_B3, lane);

        // scatter params: STS.64 pairs (cols even -> 8B aligned), stride 28
#pragma unroll
        for (int m = 0; m < 2; m++) {
            int r0 = wp * 32 + m * 16 + (lane >> 2);
            int q2 = 2 * (lane & 3);
#pragma unroll
            for (int nt = 0; nt < 3; nt++) {
                int col = nt * 8 + q2;
                *(float2*)&pbuf[r0 * PSTRIDE + col]       = make_float2(c[m][nt][0], c[m][nt][1]);
                *(float2*)&pbuf[(r0 + 8) * PSTRIDE + col] = make_float2(c[m][nt][2], c[m][nt][3]);
            }
        }
        __syncwarp();

        // gather own row via 6x LDS.128 (rows 16B-aligned, stride-28 conflict-free)
        {
            const float* b3l = b3 + l * NP;
            const float4* pr = (const float4*)&pbuf[t * PSTRIDE];
            float4 q0 = pr[0], q1 = pr[1], q2v = pr[2], q3 = pr[3], q4 = pr[4], q5 = pr[5];
            float p[24];
            p[0] = q0.x;  p[1] = q0.y;  p[2] = q0.z;  p[3] = q0.w;
            p[4] = q1.x;  p[5] = q1.y;  p[6] = q1.z;  p[7] = q1.w;
            p[8] = q2v.x; p[9] = q2v.y; p[10] = q2v.z; p[11] = q2v.w;
            p[12] = q3.x; p[13] = q3.y; p[14] = q3.z; p[15] = q3.w;
            p[16] = q4.x; p[17] = q4.y; p[18] = q4.z; p[19] = q4.w;
            p[20] = q5.x; p[21] = q5.y; p[22] = q5.z;
#pragma unroll
            for (int j = 0; j < NP; j++) p[j] += __ldg(&b3l[j]);
            float ld;
            float xv = __ldg(&x[(size_t)b * 32 + l + 1]);
            zout[(size_t)b * DIMN + l + 1] = spline_fwd(xv, p, &ld);
            ldacc += ld;
        }
        __syncwarp();   // protect pbuf before next layer's scatter
    }

    g_ldpart[grp * BATCH + b] = ldacc;
}

extern "C" void kernel_launch(void* const* d_in, const int* in_sizes, int n_in,
                              void* d_out, int out_size) {
    const float* x          = (const float*)d_in[0];
    const float* init_param = (const float*)d_in[1];
    const float* w1 = (const float*)d_in[2];
    const float* b1 = (const float*)d_in[3];
    const float* w2 = (const float*)d_in[4];
    const float* b2 = (const float*)d_in[5];
    const float* w3 = (const float*)d_in[6];
    const float* b3 = (const float*)d_in[7];

    float* out = (float*)d_out;
    int write_ld = (out_size >= BATCH * DIMN + BATCH) ? 1 : 0;

    dim3 pgrid(LNUM, 4);
    nsf_prep_kernel<<<pgrid, 128>>>(w1, b1, w2, b2, w3);
    dim3 grid(BATCH / 128, NGRP);
    nsf_mma_kernel<<<grid, 128>>>(x, init_param, b3, out);
    if (write_ld)
        nsf_ld_reduce<<<BATCH / 256, 256>>>(out + (size_t)BATCH * DIMN);
}